// round 12
// baseline (speedup 1.0000x reference)
#include <cuda_runtime.h>
#include <cuda_bf16.h>
#include <cstdint>

#define BATCH 4096

// ---------------- scratch (device globals; no allocation allowed) ----------
__device__ __align__(16) __nv_bfloat16 g_h1hi[BATCH * 10368]; // padded 18x18 pos x 32ch
__device__ __align__(16) __nv_bfloat16 g_h1lo[BATCH * 10368];
__device__ __align__(16) __nv_bfloat16 g_w2hi[4 * 64 * 288];  // [e][oc][k=tap*32+ic]
__device__ __align__(16) __nv_bfloat16 g_w2lo[4 * 64 * 288];
__device__ __align__(16) __nv_bfloat16 g_w1hi[4 * 32 * 40];   // [e][oc][k pad 40]
__device__ __align__(16) __nv_bfloat16 g_w1lo[4 * 32 * 40];
__device__ __align__(16) __nv_bfloat16 g_wrhi[16 * 40];       // router conv w hi
__device__ __align__(16) __nv_bfloat16 g_wrlo[16 * 40];
__device__ __align__(16) __nv_bfloat16 g_wf1hi[4 * 128 * 4096]; // fc1 w hi
__device__ __align__(16) __nv_bfloat16 g_wf1lo[4 * 128 * 4096]; // fc1 w lo
__device__ __align__(16) __nv_bfloat16 g_h2hi[BATCH * 4096];  // (b, oc*64+py*8+px)
__device__ __align__(16) __nv_bfloat16 g_h2lo[BATCH * 4096];
__device__ float g_fc1part[8 * BATCH * 128];  // split-K partials [ks][b][n]
__device__ int   g_expert[BATCH];
__device__ float g_gatew[BATCH];
__device__ int   g_count[4];
__device__ int   g_list[4 * BATCH];

// ---------------- warp-MMA helpers (plain sm_80+ PTX, sm_103-safe) ---------
__device__ __forceinline__ void ldsm_x4(uint32_t* r, uint32_t addr) {
    asm volatile("ldmatrix.sync.aligned.m8n8.x4.shared.b16 {%0,%1,%2,%3}, [%4];"
                 : "=r"(r[0]), "=r"(r[1]), "=r"(r[2]), "=r"(r[3]) : "r"(addr));
}
__device__ __forceinline__ void mma16816(float* d, const uint32_t* a,
                                         uint32_t b0, uint32_t b1) {
    asm volatile("mma.sync.aligned.m16n8k16.row.col.f32.bf16.bf16.f32 "
                 "{%0,%1,%2,%3}, {%4,%5,%6,%7}, {%8,%9}, {%0,%1,%2,%3};"
                 : "+f"(d[0]), "+f"(d[1]), "+f"(d[2]), "+f"(d[3])
                 : "r"(a[0]), "r"(a[1]), "r"(a[2]), "r"(a[3]), "r"(b0), "r"(b1));
}
__device__ __forceinline__ uint32_t smem_u32(const void* p) {
    uint32_t a;
    asm("{ .reg .u64 t; cvta.to.shared.u64 t, %1; cvt.u32.u64 %0, t; }" : "=r"(a) : "l"(p));
    return a;
}

// ---------------- Kernel P: counters + ALL weight hi/lo splits -------------
__global__ void __launch_bounds__(256) k_prep(const float* __restrict__ ew2,
                                              const float* __restrict__ ew1,
                                              const float* __restrict__ ewf1,
                                              const float* __restrict__ gwc) {
    int id = blockIdx.x * 256 + threadIdx.x;
    if (id < 4) g_count[id] = 0;
    if (id < 73728) {                        // conv2: 4*64*288
        int e = id / 18432, r = id % 18432, oc = r / 288, k = r % 288;
        int tap = k >> 5, ic = k & 31;
        float w = ew2[(((size_t)e * 64 + oc) * 32 + ic) * 9 + tap];
        __nv_bfloat16 hi = __float2bfloat16(w);
        g_w2hi[id] = hi;
        g_w2lo[id] = __float2bfloat16(w - __bfloat162float(hi));
    } else if (id < 78848) {                 // conv1: 4*32*40
        int id1 = id - 73728;
        int e = id1 / 1280, r = id1 % 1280, oc = r / 40, k = r % 40;
        float w = 0.f;
        if (k < 27) { int ic = k / 9, tap = k % 9; w = ew1[(((size_t)e * 32 + oc) * 3 + ic) * 9 + tap]; }
        __nv_bfloat16 hi = __float2bfloat16(w);
        g_w1hi[id1] = hi;
        g_w1lo[id1] = __float2bfloat16(w - __bfloat162float(hi));
    } else if (id < 78848 + 2097152) {       // fc1: 4*128*4096 (layout identical)
        int id2 = id - 78848;
        float w = ewf1[id2];
        __nv_bfloat16 hi = __float2bfloat16(w);
        g_wf1hi[id2] = hi;
        g_wf1lo[id2] = __float2bfloat16(w - __bfloat162float(hi));
    } else if (id < 2176640) {               // router conv: 16*40
        int id3 = id - 2176000;
        int oc = id3 / 40, k = id3 % 40;
        float w = 0.f;
        if (k < 27) { int ic = k / 9, tap = k % 9; w = gwc[(oc * 3 + ic) * 9 + tap]; }
        __nv_bfloat16 hi = __float2bfloat16(w);
        g_wrhi[id3] = hi;
        g_wrlo[id3] = __float2bfloat16(w - __bfloat162float(hi));
    }
}

// ---------------- Kernel FRONT: router(mma+guard)+gate+top1, conv1(mma) ----
__global__ void __launch_bounds__(256) k_front(
    const float* __restrict__ x,
    const float* __restrict__ gw,   const float* __restrict__ gb,
    const float* __restrict__ gwfc, const float* __restrict__ gbfc,
    const float* __restrict__ eb1,
    float* __restrict__ out_probs) {
    __shared__ __align__(16) float xs[3 * 34 * 34];
    __shared__ __align__(16) float wsr[27 * 20];
    __shared__ float bsr16[16];
    __shared__ float wsum[8][16];
    __shared__ float pooled_s[16];
    __shared__ int   e_s;
    __shared__ int   flag_s;
    __shared__ __align__(16) __nv_bfloat16 Abuf[2 * 128 * 40];  // hi | lo (10240 B each)
    __shared__ __align__(16) __nv_bfloat16 W1s[2 * 32 * 40];    // hi | lo (2560 B each)
    __shared__ float bs1[32];

    int b = blockIdx.x, tid = threadIdx.x;
    int lane = tid & 31, w = tid >> 5;

    // zero halo of padded 18x18x32 bf16 h1 output (u32 = 2ch granularity)
    {
        uint32_t* ph = (uint32_t*)(g_h1hi + (size_t)b * 10368);
        uint32_t* pl = (uint32_t*)(g_h1lo + (size_t)b * 10368);
        for (int i = tid; i < 1088; i += 256) {
            int off;
            if (i < 288)       off = i;
            else if (i < 576)  off = 17 * 288 + (i - 288);
            else if (i < 832) { int r = 1 + ((i - 576) >> 4); off = (r * 18) * 16 + ((i - 576) & 15); }
            else              { int r = 1 + ((i - 832) >> 4); off = (r * 18 + 17) * 16 + ((i - 832) & 15); }
            ph[off] = 0u; pl[off] = 0u;
        }
    }

    for (int i = tid; i < 3 * 34 * 34; i += 256) xs[i] = 0.f;
    for (int i = tid; i < 432; i += 256) { int oc = i / 27, r = i - oc * 27; wsr[r * 20 + oc] = gw[i]; }
    if (tid < 16) bsr16[tid] = gb[tid];
    // router weights into W1s: hi rows [0,1280) B, lo at +2560 B
    {
        const uint4* whi = (const uint4*)g_wrhi;
        const uint4* wlo = (const uint4*)g_wrlo;
        uint4* dst = (uint4*)W1s;
        for (int i = tid; i < 80; i += 256) { dst[i] = whi[i]; dst[160 + i] = wlo[i]; }
    }
    __syncthreads();
    const float* xg = x + (size_t)b * 3072;
    for (int i = tid; i < 3072; i += 256) {
        int ic = i >> 10, rem = i & 1023, yy = rem >> 5, xx = rem & 31;
        xs[ic * 1156 + (yy + 1) * 34 + xx + 1] = xg[i];
    }
    __syncthreads();

    uint32_t Ab = smem_u32(Abuf);
    uint32_t Wb = smem_u32(W1s);
    int q = lane >> 3, rowid = lane & 7;
    uint32_t abase = Ab + (uint32_t)((16 * w + (lane & 15)) * 80 + (lane >> 4) * 16);

    // hoist router B frags (16 oc = 2 n-tiles; same for all chunks)
    uint32_t bhr[2][4], blr[2][4];
#pragma unroll
    for (int kh = 0; kh < 2; kh++) {
        int koff2 = (kh * 16 + (q & 1) * 8) * 2;
        uint32_t bd = Wb + (uint32_t)(((q >> 1) * 8 + rowid) * 80 + koff2);
        ldsm_x4(bhr[kh], bd);
        ldsm_x4(blr[kh], bd + 2560);
    }

    // ---- PASS 1: router conv via mma, pooled accumulation ----
    float rp[2][2] = {{0.f, 0.f}, {0.f, 0.f}};
    for (int c = 0; c < 8; c++) {
        {   // build A chunk [128 rows, 32 K] hi+lo
            int m = tid >> 1, kh = tid & 1;
            int wm = m >> 4, r = m & 15;
            int ypix = 4 * c + 2 * (wm & 1) + (r >> 3);
            int xpix = 8 * (wm >> 1) + (r & 7);
            const float* xb = &xs[ypix * 34 + xpix];
            __nv_bfloat162* dh = (__nv_bfloat162*)&Abuf[m * 40 + kh * 16];
            __nv_bfloat162* dl = (__nv_bfloat162*)&Abuf[128 * 40 + m * 40 + kh * 16];
            float v[16];
            if (kh == 0) {
#pragma unroll
                for (int kk = 0; kk < 16; kk++) {
                    int ic = kk / 9, tap = kk % 9;
                    v[kk] = xb[ic * 1156 + (tap / 3) * 34 + (tap % 3)];
                }
            } else {
#pragma unroll
                for (int kk = 0; kk < 16; kk++) {
                    int k = 16 + kk;
                    if (k < 27) {
                        int ic = k / 9, tap = k % 9;
                        v[kk] = xb[ic * 1156 + (tap / 3) * 34 + (tap % 3)];
                    } else v[kk] = 0.f;
                }
            }
#pragma unroll
            for (int i2 = 0; i2 < 8; i2++) {
                __nv_bfloat16 h0 = __float2bfloat16(v[2 * i2]);
                __nv_bfloat16 h1 = __float2bfloat16(v[2 * i2 + 1]);
                __nv_bfloat162 hv; hv.x = h0; hv.y = h1;
                dh[i2] = hv;
                __nv_bfloat162 lv;
                lv.x = __float2bfloat16(v[2 * i2]     - __bfloat162float(h0));
                lv.y = __float2bfloat16(v[2 * i2 + 1] - __bfloat162float(h1));
                dl[i2] = lv;
            }
        }
        __syncthreads();

        float accr[2][4];
#pragma unroll
        for (int nt = 0; nt < 2; nt++)
#pragma unroll
            for (int i = 0; i < 4; i++) accr[nt][i] = 0.f;
#pragma unroll
        for (int kh = 0; kh < 2; kh++) {
            uint32_t ah[4], al[4];
            ldsm_x4(ah, abase + kh * 32);
            ldsm_x4(al, abase + 10240 + kh * 32);
#pragma unroll
            for (int nt = 0; nt < 2; nt++) {
                mma16816(accr[nt], ah, bhr[kh][2 * nt], bhr[kh][2 * nt + 1]);
                mma16816(accr[nt], al, bhr[kh][2 * nt], bhr[kh][2 * nt + 1]);
                mma16816(accr[nt], ah, blr[kh][2 * nt], blr[kh][2 * nt + 1]);
            }
        }
#pragma unroll
        for (int nt = 0; nt < 2; nt++) {
            int n0 = nt * 8 + 2 * (lane & 3);
            float b0 = bsr16[n0], b1 = bsr16[n0 + 1];
            rp[nt][0] += fmaxf(accr[nt][0] + b0, 0.f) + fmaxf(accr[nt][2] + b0, 0.f);
            rp[nt][1] += fmaxf(accr[nt][1] + b1, 0.f) + fmaxf(accr[nt][3] + b1, 0.f);
        }
        __syncthreads();
    }

    // reduce pooled: lanes {l, l+4, ..., l+28} -> lane<4
#pragma unroll
    for (int nt = 0; nt < 2; nt++)
#pragma unroll
        for (int col = 0; col < 2; col++) {
            float v = rp[nt][col];
            v += __shfl_down_sync(0xffffffffu, v, 16);
            v += __shfl_down_sync(0xffffffffu, v, 8);
            v += __shfl_down_sync(0xffffffffu, v, 4);
            if (lane < 4) wsum[w][nt * 8 + 2 * lane + col] = v;
        }
    __syncthreads();
    if (tid < 16) {
        float s = 0.f;
#pragma unroll
        for (int ww = 0; ww < 8; ww++) s += wsum[ww][tid];
        pooled_s[tid] = s * (1.0f / 1024.0f);
    }
    __syncthreads();

    // margin check (thread 0)
    if (tid == 0) {
        float lg[4];
#pragma unroll
        for (int e = 0; e < 4; e++) {
            float s = gbfc[e];
#pragma unroll
            for (int k = 0; k < 16; k++) s += pooled_s[k] * gwfc[e * 16 + k];
            lg[e] = s;
        }
        float best = -1e30f, second = -1e30f;
#pragma unroll
        for (int e = 0; e < 4; e++) {
            if (lg[e] > best) { second = best; best = lg[e]; }
            else if (lg[e] > second) second = lg[e];
        }
        flag_s = (best - second) < 1e-4f;
    }
    __syncthreads();

    // exact scalar fallback when top-2 margin is too small
    int og = tid >> 7, ppx = tid & 127, px = ppx & 31, yp = ppx >> 5;
    if (flag_s) {
        float bsr[8];
#pragma unroll
        for (int j = 0; j < 8; j++) bsr[j] = bsr16[og * 8 + j];
        float psum[8];
#pragma unroll
        for (int j = 0; j < 8; j++) psum[j] = 0.f;
        for (int strip = 0; strip < 4; strip++) {
            int y0 = strip * 8 + yp * 2;
            float a0[8], a1[8];
#pragma unroll
            for (int j = 0; j < 8; j++) { a0[j] = 0.f; a1[j] = 0.f; }
            for (int ic = 0; ic < 3; ic++) {
                const float* xb = &xs[ic * 1156];
#pragma unroll
                for (int dy = 0; dy < 3; dy++) {
                    const float* r0 = &xb[(y0 + dy) * 34 + px];
                    const float* r1 = r0 + 34;
                    const float* wr = &wsr[(ic * 9 + dy * 3) * 20 + og * 8];
#pragma unroll
                    for (int dx = 0; dx < 3; dx++) {
                        float v0 = r0[dx], v1 = r1[dx];
                        float wv[8];
                        *(float4*)&wv[0] = *(const float4*)&wr[dx * 20];
                        *(float4*)&wv[4] = *(const float4*)&wr[dx * 20 + 4];
#pragma unroll
                        for (int j = 0; j < 8; j++) { a0[j] += v0 * wv[j]; a1[j] += v1 * wv[j]; }
                    }
                }
            }
#pragma unroll
            for (int j = 0; j < 8; j++)
                psum[j] += fmaxf(a0[j] + bsr[j], 0.f) + fmaxf(a1[j] + bsr[j], 0.f);
        }
#pragma unroll
        for (int j = 0; j < 8; j++) {
            float v = psum[j];
#pragma unroll
            for (int o = 16; o > 0; o >>= 1) v += __shfl_down_sync(0xffffffffu, v, o);
            if (lane == 0) wsum[w][j] = v;
        }
        __syncthreads();
        if (tid < 16) {
            int ogi = tid >> 3, j = tid & 7;
            float s = 0.f;
#pragma unroll
            for (int ww = 0; ww < 4; ww++) s += wsum[ogi * 4 + ww][j];
            pooled_s[ogi * 8 + j] = s * (1.0f / 1024.0f);
        }
        __syncthreads();
    }

    // ---- final gate + softmax + top1 + compaction (thread 0) ----
    if (tid == 0) {
        float lg[4];
#pragma unroll
        for (int e = 0; e < 4; e++) {
            float s = gbfc[e];
#pragma unroll
            for (int k = 0; k < 16; k++) s += pooled_s[k] * gwfc[e * 16 + k];
            lg[e] = s;
        }
        int am = 0; float best = lg[0];
#pragma unroll
        for (int e = 1; e < 4; e++) if (lg[e] > best) { best = lg[e]; am = e; }
        float ex[4], ssum = 0.f;
#pragma unroll
        for (int e = 0; e < 4; e++) { ex[e] = expf(lg[e] - best); ssum += ex[e]; }
        float inv = 1.0f / ssum;
#pragma unroll
        for (int e = 0; e < 4; e++) out_probs[b * 4 + e] = ex[e] * inv;
        g_expert[b] = am;
        g_gatew[b]  = ex[am] * inv;
        int pos = atomicAdd(&g_count[am], 1);
        g_list[am * BATCH + pos] = b;
        e_s = am;
    }
    __syncthreads();
    int e = e_s;

    // ---- load conv1 weights (hi/lo, [32 oc][40 k] rows = 80 B) ----
    {
        const uint4* whi = (const uint4*)(g_w1hi + (size_t)e * 1280);
        const uint4* wlo = (const uint4*)(g_w1lo + (size_t)e * 1280);
        uint4* dst = (uint4*)W1s;
        for (int i = tid; i < 160; i += 256) { dst[i] = whi[i]; dst[160 + i] = wlo[i]; }
        for (int i = tid; i < 32; i += 256) bs1[i] = eb1[e * 32 + i];
    }
    __syncthreads();

    // ---- PASS 2: conv1 via mma: 8 chunks of 128 pixels ----
    for (int c = 0; c < 8; c++) {
        {
            int m = tid >> 1, kh = tid & 1;
            int wm = m >> 4, r = m & 15;
            int ypix = 4 * c + 2 * (wm & 1) + (r >> 3);
            int xpix = 8 * (wm >> 1) + (r & 7);
            const float* xb = &xs[ypix * 34 + xpix];
            __nv_bfloat162* dh = (__nv_bfloat162*)&Abuf[m * 40 + kh * 16];
            __nv_bfloat162* dl = (__nv_bfloat162*)&Abuf[128 * 40 + m * 40 + kh * 16];
            float v[16];
            if (kh == 0) {
#pragma unroll
                for (int kk = 0; kk < 16; kk++) {
                    int ic = kk / 9, tap = kk % 9;
                    v[kk] = xb[ic * 1156 + (tap / 3) * 34 + (tap % 3)];
                }
            } else {
#pragma unroll
                for (int kk = 0; kk < 16; kk++) {
                    int k = 16 + kk;
                    if (k < 27) {
                        int ic = k / 9, tap = k % 9;
                        v[kk] = xb[ic * 1156 + (tap / 3) * 34 + (tap % 3)];
                    } else v[kk] = 0.f;
                }
            }
#pragma unroll
            for (int i2 = 0; i2 < 8; i2++) {
                __nv_bfloat16 h0 = __float2bfloat16(v[2 * i2]);
                __nv_bfloat16 h1 = __float2bfloat16(v[2 * i2 + 1]);
                __nv_bfloat162 hv; hv.x = h0; hv.y = h1;
                dh[i2] = hv;
                __nv_bfloat162 lv;
                lv.x = __float2bfloat16(v[2 * i2]     - __bfloat162float(h0));
                lv.y = __float2bfloat16(v[2 * i2 + 1] - __bfloat162float(h1));
                dl[i2] = lv;
            }
        }
        __syncthreads();

        float acc[4][4];
#pragma unroll
        for (int nt = 0; nt < 4; nt++)
#pragma unroll
            for (int i = 0; i < 4; i++) acc[nt][i] = 0.f;

#pragma unroll
        for (int kh = 0; kh < 2; kh++) {
            uint32_t ah[4], al[4];
            ldsm_x4(ah, abase + kh * 32);
            ldsm_x4(al, abase + 10240 + kh * 32);
            uint32_t bh[8], bl[8];
            int koff2 = (kh * 16 + (q & 1) * 8) * 2;
#pragma unroll
            for (int j = 0; j < 2; j++) {
                uint32_t bd = Wb + (uint32_t)(((2 * j + (q >> 1)) * 8 + rowid) * 80 + koff2);
                ldsm_x4(&bh[4 * j], bd);
                ldsm_x4(&bl[4 * j], bd + 2560);
            }
#pragma unroll
            for (int nt = 0; nt < 4; nt++) {
                mma16816(acc[nt], ah, bh[2 * nt], bh[2 * nt + 1]);
                mma16816(acc[nt], al, bh[2 * nt], bh[2 * nt + 1]);
                mma16816(acc[nt], ah, bl[2 * nt], bl[2 * nt + 1]);
            }
        }

        {   // y-pool in-thread, x-pool shfl, bias, relu, hi/lo store
            int r1 = lane >> 2;
            bool active = (r1 & 1) == 0;
            int p = w & 1, o = w >> 1;
            int py = 2 * c + p;
            int pxp = 4 * o + (r1 >> 1);
            size_t base = (size_t)b * 10368 + (size_t)((py + 1) * 18 + (pxp + 1)) * 32;
#pragma unroll
            for (int nt = 0; nt < 4; nt++) {
                int oc = nt * 8 + 2 * (lane & 3);
                float m0 = fmaxf(acc[nt][0], acc[nt][2]);
                float m1 = fmaxf(acc[nt][1], acc[nt][3]);
                m0 = fmaxf(m0, __shfl_xor_sync(0xffffffffu, m0, 4));
                m1 = fmaxf(m1, __shfl_xor_sync(0xffffffffu, m1, 4));
                if (active) {
                    float v0 = fmaxf(m0 + bs1[oc], 0.f);
                    float v1 = fmaxf(m1 + bs1[oc + 1], 0.f);
                    __nv_bfloat16 h0 = __float2bfloat16(v0);
                    __nv_bfloat16 h1 = __float2bfloat16(v1);
                    __nv_bfloat162 hv; hv.x = h0; hv.y = h1;
                    *(__nv_bfloat162*)&g_h1hi[base + oc] = hv;
                    __nv_bfloat162 lv;
                    lv.x = __float2bfloat16(v0 - __bfloat162float(h0));
                    lv.y = __float2bfloat16(v1 - __bfloat162float(h1));
                    *(__nv_bfloat162*)&g_h1lo[base + oc] = lv;
                }
            }
        }
        __syncthreads();
    }
}

// ---------------- Kernel E: conv2 via mma.sync bf16x3, oc quarters ---------
#define C2_H1LO   25920
#define C2_B_OFF  51840
#define C2_BPART  9472
#define C2_BIAS   70784
#define C2_SMEM   70912

__global__ void __launch_bounds__(256, 3) k_conv2m(const float* __restrict__ eb2) {
    extern __shared__ __align__(16) char sm[];
    int quarter = blockIdx.x, b = blockIdx.y, tid = threadIdx.x;
    int w = tid >> 5, lane = tid & 31;
    int e = g_expert[b];

    {   // h1 hi/lo: [324 pos][32 ch] -> 80 B rows
        const uint4* shi = (const uint4*)(g_h1hi + (size_t)b * 10368);
        const uint4* slo = (const uint4*)(g_h1lo + (size_t)b * 10368);
        for (int i = tid; i < 1296; i += 256) {
            int pos = i >> 2, ch = i & 3;
            *(uint4*)(sm + pos * 80 + ch * 16) = shi[i];
            *(uint4*)(sm + C2_H1LO + pos * 80 + ch * 16) = slo[i];
        }
        const uint4* whi = (const uint4*)(g_w2hi + (size_t)e * 18432);
        const uint4* wlo = (const uint4*)(g_w2lo + (size_t)e * 18432);
        for (int i = tid; i < 576; i += 256) {
            int ocl = i / 36, ch = i % 36;
            int src = (quarter * 16 + ocl) * 36 + ch;
            *(uint4*)(sm + C2_B_OFF + ocl * 592 + ch * 16) = whi[src];
            *(uint4*)(sm + C2_B_OFF + C2_BPART + ocl * 592 + ch * 16) = wlo[src];
        }
        float* bs2 = (float*)(sm + C2_BIAS);
        for (int i = tid; i < 16; i += 256) bs2[i] = eb2[e * 64 + quarter * 16 + i];
    }
    __syncthreads();

    uint32_t h1b = smem_u32(sm);
    uint32_t bwb = h1b + C2_B_OFF;

    float acc[2][2][4];
#pragma unroll
    for (int f = 0; f < 2; f++)
#pragma unroll
        for (int nt = 0; nt < 2; nt++)
#pragma unroll
            for (int i = 0; i < 4; i++) acc[f][nt][i] = 0.f;

    int y0 = 2 * w;
    int xl = lane & 15, sel = lane >> 4;
    int q = lane >> 3, rowid = lane & 7;

    const int DY[9] = {0, 0, 0, 1, 1, 1, 2, 2, 2};
    const int DX[9] = {0, 1, 2, 0, 1, 2, 0, 1, 2};

    for (int s = 0; s < 18; s++) {
        int tap = s >> 1, ichalf = s & 1;
        int dy = DY[tap], dx = DX[tap];

        uint32_t ah[2][4], al[2][4];
#pragma unroll
        for (int f = 0; f < 2; f++) {
            int pos = (y0 + f + dy) * 18 + (xl + dx);
            uint32_t ad = h1b + (uint32_t)(pos * 80 + ichalf * 32 + sel * 16);
            ldsm_x4(ah[f], ad);
            ldsm_x4(al[f], ad + C2_H1LO);
        }

        uint32_t bh[4], bl[4];
        {
            int koff = s * 16 + (q & 1) * 8;
            uint32_t bd = bwb + (uint32_t)((((q >> 1) * 8 + rowid) * 296 + koff) * 2);
            ldsm_x4(bh, bd);
            ldsm_x4(bl, bd + C2_BPART);
        }

#pragma unroll
        for (int f = 0; f < 2; f++)
#pragma unroll
            for (int nt = 0; nt < 2; nt++) {
                mma16816(acc[f][nt], ah[f], bh[2 * nt], bh[2 * nt + 1]);
                mma16816(acc[f][nt], al[f], bh[2 * nt], bh[2 * nt + 1]);
                mma16816(acc[f][nt], ah[f], bl[2 * nt], bl[2 * nt + 1]);
            }
    }

    // epilogue: y-pool, x-pool, bias, relu, bf16 hi/lo store
    const float* bs2 = (const float*)(sm + C2_BIAS);
    bool active = ((lane >> 2) & 1) == 0;
    int px1 = (lane >> 2) >> 1;
    size_t ob = (size_t)b * 4096 + (size_t)(quarter * 16) * 64 + w * 8;
#pragma unroll
    for (int nt = 0; nt < 2; nt++) {
        int ocl = nt * 8 + (lane & 3) * 2;
        float bA = bs2[ocl], bB = bs2[ocl + 1];
        float v[4];
#pragma unroll
        for (int i = 0; i < 4; i++) {
            float m = fmaxf(acc[0][nt][i], acc[1][nt][i]);
            m = fmaxf(m, __shfl_xor_sync(0xffffffffu, m, 4));
            v[i] = m;
        }
        if (active) {
            float r0 = fmaxf(v[0] + bA, 0.f), r1 = fmaxf(v[1] + bB, 0.f);
            float r2 = fmaxf(v[2] + bA, 0.f), r3 = fmaxf(v[3] + bB, 0.f);
            size_t i00 = ob + (size_t)ocl * 64 + px1;
            size_t i10 = ob + (size_t)(ocl + 1) * 64 + px1;
            __nv_bfloat16 h;
            h = __float2bfloat16(r0); g_h2hi[i00] = h;     g_h2lo[i00] = __float2bfloat16(r0 - __bfloat162float(h));
            h = __float2bfloat16(r1); g_h2hi[i10] = h;     g_h2lo[i10] = __float2bfloat16(r1 - __bfloat162float(h));
            h = __float2bfloat16(r2); g_h2hi[i00 + 4] = h; g_h2lo[i00 + 4] = __float2bfloat16(r2 - __bfloat162float(h));
            h = __float2bfloat16(r3); g_h2hi[i10 + 4] = h; g_h2lo[i10 + 4] = __float2bfloat16(r3 - __bfloat162float(h));
        }
    }
}

// ---------------- Kernel F1: fc1 stage 1 — M=64 tiles x K-eighth -----------
// grid (64, 4, 8): x = sample group, y = expert, z = K-split (512 K each).
#define FC_A_OFF 36864
#define FC_SMEM  55296

__global__ void __launch_bounds__(256, 2) k_fc1(float* __restrict__ dummy) {
    extern __shared__ __align__(16) char smc[];
    __shared__ int sb[64];

    int g = blockIdx.x, e = blockIdx.y, ks = blockIdx.z, tid = threadIdx.x;
    int lane = tid & 31, w = tid >> 5;
    int cnt = g_count[e];
    if (g * 64 >= cnt) return;
    if (tid < 64) {
        int slot = g * 64 + tid;
        sb[tid] = g_list[e * BATCH + ((slot < cnt) ? slot : (g * 64))];
    }
    __syncthreads();

    uint32_t Wb = smem_u32(smc);
    uint32_t Ab = Wb + FC_A_OFF;
    int q = lane >> 3, rowid = lane & 7;

    float acc[4][2][4];
#pragma unroll
    for (int mf = 0; mf < 4; mf++)
#pragma unroll
        for (int nt = 0; nt < 2; nt++)
#pragma unroll
            for (int i = 0; i < 4; i++) acc[mf][nt][i] = 0.f;

    const uint4* whig = (const uint4*)(g_wf1hi + (size_t)e * 524288);
    const uint4* wlog = (const uint4*)(g_wf1lo + (size_t)e * 524288);

    for (int cc = 0; cc < 8; cc++) {
        int c = ks * 8 + cc;
#pragma unroll
        for (int t = 0; t < 4; t++) {
            int j = t * 256 + tid;
            int n = j >> 3, k8 = j & 7;
            size_t gi = (size_t)n * 512 + c * 8 + k8;
            *(uint4*)(smc + n * 144 + k8 * 16) = whig[gi];
            *(uint4*)(smc + 18432 + n * 144 + k8 * 16) = wlog[gi];
        }
#pragma unroll
        for (int t = 0; t < 2; t++) {
            int j = t * 256 + tid;
            int s = j >> 3, k8 = j & 7;
            size_t gi = (size_t)sb[s] * 4096 + c * 64 + k8 * 8;
            *(uint4*)(smc + FC_A_OFF + s * 144 + k8 * 16) = *(const uint4*)&g_h2hi[gi];
            *(uint4*)(smc + FC_A_OFF + 9216 + s * 144 + k8 * 16) = *(const uint4*)&g_h2lo[gi];
        }
        __syncthreads();

#pragma unroll
        for (int k16 = 0; k16 < 4; k16++) {
            uint32_t bh[4], bl[4];
            uint32_t bd = Wb + (uint32_t)((w * 16 + (q >> 1) * 8 + rowid) * 144 + k16 * 32 + (q & 1) * 16);
            ldsm_x4(bh, bd);
            ldsm_x4(bl, bd + 18432);
#pragma unroll
            for (int mf = 0; mf < 4; mf++) {
                uint32_t ah[4], al[4];
                uint32_t ad = Ab + (uint32_t)((mf * 16 + (lane & 15)) * 144 + k16 * 32 + (lane >> 4) * 16);
                ldsm_x4(ah, ad);
                ldsm_x4(al, ad + 9216);
#pragma unroll
                for (int nt = 0; nt < 2; nt++) {
                    mma16816(acc[mf][nt], ah, bh[2 * nt], bh[2 * nt + 1]);
                    mma16816(acc[mf][nt], al, bh[2 * nt], bh[2 * nt + 1]);
                    mma16816(acc[mf][nt], ah, bl[2 * nt], bl[2 * nt + 1]);
                }
            }
        }
        __syncthreads();
    }

    float* pout = g_fc1part + (size_t)ks * (BATCH * 128);
    int r1 = lane >> 2, ccn = 2 * (lane & 3);
#pragma unroll
    for (int mf = 0; mf < 4; mf++) {
        int row0 = mf * 16 + r1, row1 = row0 + 8;
        bool ok0 = (g * 64 + row0) < cnt;
        bool ok1 = (g * 64 + row1) < cnt;
        int b0 = sb[row0], b1 = sb[row1];
#pragma unroll
        for (int nt = 0; nt < 2; nt++) {
            int n = w * 16 + nt * 8 + ccn;
            if (ok0) {
                pout[(size_t)b0 * 128 + n]     = acc[mf][nt][0];
                pout[(size_t)b0 * 128 + n + 1] = acc[mf][nt][1];
            }
            if (ok1) {
                pout[(size_t)b1 * 128 + n]     = acc[mf][nt][2];
                pout[(size_t)b1 * 128 + n + 1] = acc[mf][nt][3];
            }
        }
    }
}

// ---------------- Kernel F2: combine K-splits + bias/relu + fc2 + aux ------
__global__ void __launch_bounds__(256) k_fc2(
    const float* __restrict__ bf1,
    const float* __restrict__ wf2, const float* __restrict__ bf2,
    const float* __restrict__ probs,
    float* __restrict__ out_final, float* __restrict__ out_aux) {
    __shared__ float w2all[5120];
    __shared__ float fs[32 * 129];
    __shared__ float sred[256][4];
    int blk = blockIdx.x, tid = threadIdx.x;

    if (blk == 0) {
        float s[4] = {0.f, 0.f, 0.f, 0.f};
        for (int b = tid; b < BATCH; b += 256) {
            float4 p = *(const float4*)&probs[b * 4];
            s[0] += p.x; s[1] += p.y; s[2] += p.z; s[3] += p.w;
        }
#pragma unroll
        for (int k = 0; k < 4; k++) sred[tid][k] = s[k];
        __syncthreads();
        for (int o = 128; o > 0; o >>= 1) {
            if (tid < o)
#pragma unroll
                for (int k = 0; k < 4; k++) sred[tid][k] += sred[tid + o][k];
            __syncthreads();
        }
        if (tid == 0) {
            float a = 0.f;
#pragma unroll
            for (int k = 0; k < 4; k++) {
                float d = sred[0][k] * (1.0f / BATCH) - 0.25f;
                a += d * d;
            }
            out_aux[0] = a * 0.25f;
        }
    }

    for (int i = tid; i < 5120; i += 256) w2all[i] = wf2[i];

    {
        int si = tid >> 3, seg = tid & 7;
        int b = blk * 32 + si;
        int e = g_expert[b];
        size_t base = (size_t)b * 128 + seg * 16;
#pragma unroll
        for (int qd = 0; qd < 4; qd++) {
            int n = seg * 16 + qd * 4;
            float4 s4 = *(const float4*)&g_fc1part[base + qd * 4];
#pragma unroll
            for (int ks = 1; ks < 8; ks++) {
                float4 p = *(const float4*)&g_fc1part[(size_t)ks * BATCH * 128 + base + qd * 4];
                s4.x += p.x; s4.y += p.y; s4.z += p.z; s4.w += p.w;
            }
            float4 bb = *(const float4*)&bf1[e * 128 + n];
            fs[si * 129 + n]     = fmaxf(s4.x + bb.x, 0.f);
            fs[si * 129 + n + 1] = fmaxf(s4.y + bb.y, 0.f);
            fs[si * 129 + n + 2] = fmaxf(s4.z + bb.z, 0.f);
            fs[si * 129 + n + 3] = fmaxf(s4.w + bb.w, 0.f);
        }
    }
    __syncthreads();

    for (int o = tid; o < 320; o += 256) {
        int si = o / 10, n = o - si * 10;
        int b = blk * 32 + si;
        int e = g_expert[b];
        float a = bf2[e * 10 + n];
        const float* fr = &fs[si * 129];
        const float* wr = &w2all[e * 1280 + n * 128];
#pragma unroll 8
        for (int k = 0; k < 128; k++) a += fr[k] * wr[k];
        out_final[b * 10 + n] = a * g_gatew[b];
    }
}

// ---------------- launch ---------------------------------------------------
extern "C" void kernel_launch(void* const* d_in, const int* in_sizes, int n_in,
                              void* d_out, int out_size) {
    const float* x    = (const float*)d_in[0];
    const float* gwc  = (const float*)d_in[1];
    const float* gbc  = (const float*)d_in[2];
    const float* gwfc = (const float*)d_in[3];
    const float* gbfc = (const float*)d_in[4];
    const float* ew1  = (const float*)d_in[5];
    const float* eb1  = (const float*)d_in[6];
    const float* ew2  = (const float*)d_in[7];
    const float* eb2  = (const float*)d_in[8];
    const float* ewf1 = (const float*)d_in[9];
    const float* ebf1 = (const float*)d_in[10];
    const float* ewf2 = (const float*)d_in[11];
    const float* ebf2 = (const float*)d_in[12];

    float* out       = (float*)d_out;
    float* out_final = out;
    float* out_probs = out + BATCH * 10;
    float* out_aux   = out + BATCH * 10 + BATCH * 4;

    cudaFuncSetAttribute(k_conv2m, cudaFuncAttributeMaxDynamicSharedMemorySize, C2_SMEM);
    cudaFuncSetAttribute(k_fc1,    cudaFuncAttributeMaxDynamicSharedMemorySize, FC_SMEM);

    k_prep<<<8503, 256>>>(ew2, ew1, ewf1, gwc);
    k_front<<<BATCH, 256>>>(x, gwc, gbc, gwfc, gbfc, eb1, out_probs);
    k_conv2m<<<dim3(4, BATCH), 256, C2_SMEM>>>(eb2);
    k_fc1<<<dim3(64, 4, 8), 256, FC_SMEM>>>(out_final);
    k_fc2<<<BATCH / 32, 256>>>(ebf1, ewf2, ebf2, out_probs, out_final, out_aux);
}

// round 13
// speedup vs baseline: 1.0542x; 1.0542x over previous
#include <cuda_runtime.h>
#include <cuda_bf16.h>
#include <cstdint>

#define BATCH 4096

// ---------------- scratch (device globals; no allocation allowed) ----------
__device__ __align__(16) __nv_bfloat16 g_h1hi[BATCH * 10368]; // padded 18x18 pos x 32ch
__device__ __align__(16) __nv_bfloat16 g_h1lo[BATCH * 10368];
__device__ __align__(16) __nv_bfloat16 g_w2hi[4 * 64 * 288];  // [e][oc][k=tap*32+ic]
__device__ __align__(16) __nv_bfloat16 g_w2lo[4 * 64 * 288];
__device__ __align__(16) __nv_bfloat16 g_w1hi[4 * 32 * 40];   // [e][oc][k pad 40]
__device__ __align__(16) __nv_bfloat16 g_w1lo[4 * 32 * 40];
__device__ __align__(16) __nv_bfloat16 g_wf1hi[4 * 128 * 4096]; // fc1 w hi
__device__ __align__(16) __nv_bfloat16 g_wf1lo[4 * 128 * 4096]; // fc1 w lo
__device__ __align__(16) __nv_bfloat16 g_h2hi[BATCH * 4096];  // (b, oc*64+py*8+px)
__device__ __align__(16) __nv_bfloat16 g_h2lo[BATCH * 4096];
__device__ float g_fc1part[4 * BATCH * 128];  // split-K partials [ks][b][n]
__device__ int   g_expert[BATCH];
__device__ float g_gatew[BATCH];
__device__ int   g_count[4];
__device__ int   g_list[4 * BATCH];

// ---------------- warp-MMA helpers (plain sm_80+ PTX, sm_103-safe) ---------
__device__ __forceinline__ void ldsm_x4(uint32_t* r, uint32_t addr) {
    asm volatile("ldmatrix.sync.aligned.m8n8.x4.shared.b16 {%0,%1,%2,%3}, [%4];"
                 : "=r"(r[0]), "=r"(r[1]), "=r"(r[2]), "=r"(r[3]) : "r"(addr));
}
__device__ __forceinline__ void mma16816(float* d, const uint32_t* a,
                                         uint32_t b0, uint32_t b1) {
    asm volatile("mma.sync.aligned.m16n8k16.row.col.f32.bf16.bf16.f32 "
                 "{%0,%1,%2,%3}, {%4,%5,%6,%7}, {%8,%9}, {%0,%1,%2,%3};"
                 : "+f"(d[0]), "+f"(d[1]), "+f"(d[2]), "+f"(d[3])
                 : "r"(a[0]), "r"(a[1]), "r"(a[2]), "r"(a[3]), "r"(b0), "r"(b1));
}
__device__ __forceinline__ uint32_t smem_u32(const void* p) {
    uint32_t a;
    asm("{ .reg .u64 t; cvta.to.shared.u64 t, %1; cvt.u32.u64 %0, t; }" : "=r"(a) : "l"(p));
    return a;
}

// ---------------- Kernel P: counters + ALL weight hi/lo splits -------------
// fc1 portion vectorized: one thread = 4 consecutive floats (float4).
__global__ void __launch_bounds__(256) k_prep(const float* __restrict__ ew2,
                                              const float* __restrict__ ew1,
                                              const float* __restrict__ ewf1) {
    int id = blockIdx.x * 256 + threadIdx.x;
    if (id < 4) g_count[id] = 0;
    if (id < 73728) {                        // conv2: 4*64*288
        int e = id / 18432, r = id % 18432, oc = r / 288, k = r % 288;
        int tap = k >> 5, ic = k & 31;
        float w = ew2[(((size_t)e * 64 + oc) * 32 + ic) * 9 + tap];
        __nv_bfloat16 hi = __float2bfloat16(w);
        g_w2hi[id] = hi;
        g_w2lo[id] = __float2bfloat16(w - __bfloat162float(hi));
    } else if (id < 78848) {                 // conv1: 4*32*40
        int id1 = id - 73728;
        int e = id1 / 1280, r = id1 % 1280, oc = r / 40, k = r % 40;
        float w = 0.f;
        if (k < 27) { int ic = k / 9, tap = k % 9; w = ew1[(((size_t)e * 32 + oc) * 3 + ic) * 9 + tap]; }
        __nv_bfloat16 hi = __float2bfloat16(w);
        g_w1hi[id1] = hi;
        g_w1lo[id1] = __float2bfloat16(w - __bfloat162float(hi));
    } else if (id < 603136) {                // fc1: 4*128*4096 floats, 4 per thread
        int id2 = (id - 78848) * 4;
        float4 w4 = *(const float4*)&ewf1[id2];
        __nv_bfloat162 h01, h23, l01, l23;
        h01.x = __float2bfloat16(w4.x);
        h01.y = __float2bfloat16(w4.y);
        h23.x = __float2bfloat16(w4.z);
        h23.y = __float2bfloat16(w4.w);
        l01.x = __float2bfloat16(w4.x - __bfloat162float(h01.x));
        l01.y = __float2bfloat16(w4.y - __bfloat162float(h01.y));
        l23.x = __float2bfloat16(w4.z - __bfloat162float(h23.x));
        l23.y = __float2bfloat16(w4.w - __bfloat162float(h23.y));
        *(__nv_bfloat162*)&g_wf1hi[id2]     = h01;
        *(__nv_bfloat162*)&g_wf1hi[id2 + 2] = h23;
        *(__nv_bfloat162*)&g_wf1lo[id2]     = l01;
        *(__nv_bfloat162*)&g_wf1lo[id2 + 2] = l23;
    }
}

// ---------------- Kernel FRONT: router(scalar)+gate+top1, conv1(mma) -------
__global__ void __launch_bounds__(256) k_front(
    const float* __restrict__ x,
    const float* __restrict__ gw,   const float* __restrict__ gb,
    const float* __restrict__ gwfc, const float* __restrict__ gbfc,
    const float* __restrict__ eb1,
    float* __restrict__ out_probs) {
    __shared__ __align__(16) float xs[3 * 34 * 34];
    __shared__ __align__(16) float wsr[27 * 20];
    __shared__ float bsr16[16];
    __shared__ float wsum[8][8];
    __shared__ float pooled_s[16];
    __shared__ int   e_s;
    __shared__ __align__(16) __nv_bfloat16 Abuf[2 * 128 * 40];  // hi | lo (10240 B each)
    __shared__ __align__(16) __nv_bfloat16 W1s[2 * 32 * 40];    // hi | lo (2560 B each)
    __shared__ float bs1[32];

    int b = blockIdx.x, tid = threadIdx.x;
    int lane = tid & 31, w = tid >> 5;

    // zero halo of padded 18x18x32 bf16 h1 output (u32 = 2ch granularity)
    {
        uint32_t* ph = (uint32_t*)(g_h1hi + (size_t)b * 10368);
        uint32_t* pl = (uint32_t*)(g_h1lo + (size_t)b * 10368);
        for (int i = tid; i < 1088; i += 256) {
            int off;
            if (i < 288)       off = i;
            else if (i < 576)  off = 17 * 288 + (i - 288);
            else if (i < 832) { int r = 1 + ((i - 576) >> 4); off = (r * 18) * 16 + ((i - 576) & 15); }
            else              { int r = 1 + ((i - 832) >> 4); off = (r * 18 + 17) * 16 + ((i - 832) & 15); }
            ph[off] = 0u; pl[off] = 0u;
        }
    }

    for (int i = tid; i < 3 * 34 * 34; i += 256) xs[i] = 0.f;
    for (int i = tid; i < 432; i += 256) { int oc = i / 27, r = i - oc * 27; wsr[r * 20 + oc] = gw[i]; }
    if (tid < 16) bsr16[tid] = gb[tid];
    __syncthreads();
    const float* xg = x + (size_t)b * 3072;
    for (int i = tid; i < 3072; i += 256) {
        int ic = i >> 10, rem = i & 1023, yy = rem >> 5, xx = rem & 31;
        xs[ic * 1156 + (yy + 1) * 34 + xx + 1] = xg[i];
    }
    __syncthreads();

    // ---- router conv (3->16) + relu + avg pool (scalar, exact) ----
    int og = tid >> 7, pp = tid & 127, px = pp & 31, yp = pp >> 5;
    {
        float bsr[8];
#pragma unroll
        for (int j = 0; j < 8; j++) bsr[j] = bsr16[og * 8 + j];
        float psum[8];
#pragma unroll
        for (int j = 0; j < 8; j++) psum[j] = 0.f;

        for (int strip = 0; strip < 4; strip++) {
            int y0 = strip * 8 + yp * 2;
            float a0[8], a1[8];
#pragma unroll
            for (int j = 0; j < 8; j++) { a0[j] = 0.f; a1[j] = 0.f; }
            for (int ic = 0; ic < 3; ic++) {
                const float* xb = &xs[ic * 1156];
#pragma unroll
                for (int dy = 0; dy < 3; dy++) {
                    const float* r0 = &xb[(y0 + dy) * 34 + px];
                    const float* r1 = r0 + 34;
                    const float* wr = &wsr[(ic * 9 + dy * 3) * 20 + og * 8];
#pragma unroll
                    for (int dx = 0; dx < 3; dx++) {
                        float v0 = r0[dx], v1 = r1[dx];
                        float wv[8];
                        *(float4*)&wv[0] = *(const float4*)&wr[dx * 20];
                        *(float4*)&wv[4] = *(const float4*)&wr[dx * 20 + 4];
#pragma unroll
                        for (int j = 0; j < 8; j++) { a0[j] += v0 * wv[j]; a1[j] += v1 * wv[j]; }
                    }
                }
            }
#pragma unroll
            for (int j = 0; j < 8; j++)
                psum[j] += fmaxf(a0[j] + bsr[j], 0.f) + fmaxf(a1[j] + bsr[j], 0.f);
        }

#pragma unroll
        for (int j = 0; j < 8; j++) {
            float v = psum[j];
#pragma unroll
            for (int o = 16; o > 0; o >>= 1) v += __shfl_down_sync(0xffffffffu, v, o);
            if (lane == 0) wsum[w][j] = v;
        }
    }
    __syncthreads();
    if (tid < 16) {  // deterministic fixed-order: warps 0-3 -> og0, 4-7 -> og1
        int ogi = tid >> 3, j = tid & 7;
        float s = 0.f;
#pragma unroll
        for (int ww = 0; ww < 4; ww++) s += wsum[ogi * 4 + ww][j];
        pooled_s[ogi * 8 + j] = s * (1.0f / 1024.0f);
    }
    __syncthreads();

    // ---- gate fc + softmax + top1 + compaction (thread 0) ----
    if (tid == 0) {
        float lg[4];
#pragma unroll
        for (int e = 0; e < 4; e++) {
            float s = gbfc[e];
#pragma unroll
            for (int k = 0; k < 16; k++) s += pooled_s[k] * gwfc[e * 16 + k];
            lg[e] = s;
        }
        int am = 0; float best = lg[0];
#pragma unroll
        for (int e = 1; e < 4; e++) if (lg[e] > best) { best = lg[e]; am = e; }
        float ex[4], ssum = 0.f;
#pragma unroll
        for (int e = 0; e < 4; e++) { ex[e] = expf(lg[e] - best); ssum += ex[e]; }
        float inv = 1.0f / ssum;
#pragma unroll
        for (int e = 0; e < 4; e++) out_probs[b * 4 + e] = ex[e] * inv;
        g_expert[b] = am;
        g_gatew[b]  = ex[am] * inv;
        int pos = atomicAdd(&g_count[am], 1);
        g_list[am * BATCH + pos] = b;
        e_s = am;
    }
    __syncthreads();
    int e = e_s;

    // ---- load conv1 weights (hi/lo, [32 oc][40 k] rows = 80 B) ----
    {
        const uint4* whi = (const uint4*)(g_w1hi + (size_t)e * 1280);
        const uint4* wlo = (const uint4*)(g_w1lo + (size_t)e * 1280);
        uint4* dst = (uint4*)W1s;
        for (int i = tid; i < 160; i += 256) { dst[i] = whi[i]; dst[160 + i] = wlo[i]; }
        for (int i = tid; i < 32; i += 256) bs1[i] = eb1[e * 32 + i];
    }
    __syncthreads();

    // ---- conv1 via mma: 8 chunks of 128 pixels (4 y-rows each) ----
    uint32_t Ab = smem_u32(Abuf);
    uint32_t Wb = smem_u32(W1s);
    int q = lane >> 3, rowid = lane & 7;
    uint32_t abase = Ab + (uint32_t)((16 * w + (lane & 15)) * 80 + (lane >> 4) * 16);

    for (int c = 0; c < 8; c++) {
        {
            int m = tid >> 1, kh = tid & 1;
            int wm = m >> 4, r = m & 15;
            int ypix = 4 * c + 2 * (wm & 1) + (r >> 3);
            int xpix = 8 * (wm >> 1) + (r & 7);
            const float* xb = &xs[ypix * 34 + xpix];
            __nv_bfloat162* dh = (__nv_bfloat162*)&Abuf[m * 40 + kh * 16];
            __nv_bfloat162* dl = (__nv_bfloat162*)&Abuf[128 * 40 + m * 40 + kh * 16];
            float v[16];
            if (kh == 0) {
#pragma unroll
                for (int kk = 0; kk < 16; kk++) {
                    int ic = kk / 9, tap = kk % 9;
                    v[kk] = xb[ic * 1156 + (tap / 3) * 34 + (tap % 3)];
                }
            } else {
#pragma unroll
                for (int kk = 0; kk < 16; kk++) {
                    int k = 16 + kk;
                    if (k < 27) {
                        int ic = k / 9, tap = k % 9;
                        v[kk] = xb[ic * 1156 + (tap / 3) * 34 + (tap % 3)];
                    } else v[kk] = 0.f;
                }
            }
#pragma unroll
            for (int i2 = 0; i2 < 8; i2++) {
                __nv_bfloat16 h0 = __float2bfloat16(v[2 * i2]);
                __nv_bfloat16 h1 = __float2bfloat16(v[2 * i2 + 1]);
                __nv_bfloat162 hv; hv.x = h0; hv.y = h1;
                dh[i2] = hv;
                __nv_bfloat162 lv;
                lv.x = __float2bfloat16(v[2 * i2]     - __bfloat162float(h0));
                lv.y = __float2bfloat16(v[2 * i2 + 1] - __bfloat162float(h1));
                dl[i2] = lv;
            }
        }
        __syncthreads();

        float acc[4][4];
#pragma unroll
        for (int nt = 0; nt < 4; nt++)
#pragma unroll
            for (int i = 0; i < 4; i++) acc[nt][i] = 0.f;

#pragma unroll
        for (int kh = 0; kh < 2; kh++) {
            uint32_t ah[4], al[4];
            ldsm_x4(ah, abase + kh * 32);
            ldsm_x4(al, abase + 10240 + kh * 32);
            uint32_t bh[8], bl[8];
            int koff2 = (kh * 16 + (q & 1) * 8) * 2;
#pragma unroll
            for (int j = 0; j < 2; j++) {
                uint32_t bd = Wb + (uint32_t)(((2 * j + (q >> 1)) * 8 + rowid) * 80 + koff2);
                ldsm_x4(&bh[4 * j], bd);
                ldsm_x4(&bl[4 * j], bd + 2560);
            }
#pragma unroll
            for (int nt = 0; nt < 4; nt++) {
                mma16816(acc[nt], ah, bh[2 * nt], bh[2 * nt + 1]);
                mma16816(acc[nt], al, bh[2 * nt], bh[2 * nt + 1]);
                mma16816(acc[nt], ah, bl[2 * nt], bl[2 * nt + 1]);
            }
        }

        {   // y-pool in-thread, x-pool shfl, bias, relu, hi/lo store
            int r1 = lane >> 2;
            bool active = (r1 & 1) == 0;
            int p = w & 1, o = w >> 1;
            int py = 2 * c + p;
            int pxp = 4 * o + (r1 >> 1);
            size_t base = (size_t)b * 10368 + (size_t)((py + 1) * 18 + (pxp + 1)) * 32;
#pragma unroll
            for (int nt = 0; nt < 4; nt++) {
                int oc = nt * 8 + 2 * (lane & 3);
                float m0 = fmaxf(acc[nt][0], acc[nt][2]);
                float m1 = fmaxf(acc[nt][1], acc[nt][3]);
                m0 = fmaxf(m0, __shfl_xor_sync(0xffffffffu, m0, 4));
                m1 = fmaxf(m1, __shfl_xor_sync(0xffffffffu, m1, 4));
                if (active) {
                    float v0 = fmaxf(m0 + bs1[oc], 0.f);
                    float v1 = fmaxf(m1 + bs1[oc + 1], 0.f);
                    __nv_bfloat16 h0 = __float2bfloat16(v0);
                    __nv_bfloat16 h1 = __float2bfloat16(v1);
                    __nv_bfloat162 hv; hv.x = h0; hv.y = h1;
                    *(__nv_bfloat162*)&g_h1hi[base + oc] = hv;
                    __nv_bfloat162 lv;
                    lv.x = __float2bfloat16(v0 - __bfloat162float(h0));
                    lv.y = __float2bfloat16(v1 - __bfloat162float(h1));
                    *(__nv_bfloat162*)&g_h1lo[base + oc] = lv;
                }
            }
        }
        __syncthreads();
    }
}

// ---------------- Kernel E: conv2 via mma.sync bf16x3, oc quarters ---------
// grid (4, BATCH): quarter-major so the 4 blocks of one sample are schedule-
// adjacent -> h1 tile L2-hits 3 of 4 loads.
#define C2_H1LO   25920
#define C2_B_OFF  51840
#define C2_BPART  9472
#define C2_BIAS   70784
#define C2_SMEM   70912

__global__ void __launch_bounds__(256, 3) k_conv2m(const float* __restrict__ eb2) {
    extern __shared__ __align__(16) char sm[];
    int quarter = blockIdx.x, b = blockIdx.y, tid = threadIdx.x;
    int w = tid >> 5, lane = tid & 31;
    int e = g_expert[b];

    {   // h1 hi/lo: [324 pos][32 ch] -> 80 B rows
        const uint4* shi = (const uint4*)(g_h1hi + (size_t)b * 10368);
        const uint4* slo = (const uint4*)(g_h1lo + (size_t)b * 10368);
        for (int i = tid; i < 1296; i += 256) {
            int pos = i >> 2, ch = i & 3;
            *(uint4*)(sm + pos * 80 + ch * 16) = shi[i];
            *(uint4*)(sm + C2_H1LO + pos * 80 + ch * 16) = slo[i];
        }
        const uint4* whi = (const uint4*)(g_w2hi + (size_t)e * 18432);
        const uint4* wlo = (const uint4*)(g_w2lo + (size_t)e * 18432);
        for (int i = tid; i < 576; i += 256) {
            int ocl = i / 36, ch = i % 36;
            int src = (quarter * 16 + ocl) * 36 + ch;
            *(uint4*)(sm + C2_B_OFF + ocl * 592 + ch * 16) = whi[src];
            *(uint4*)(sm + C2_B_OFF + C2_BPART + ocl * 592 + ch * 16) = wlo[src];
        }
        float* bs2 = (float*)(sm + C2_BIAS);
        for (int i = tid; i < 16; i += 256) bs2[i] = eb2[e * 64 + quarter * 16 + i];
    }
    __syncthreads();

    uint32_t h1b = smem_u32(sm);
    uint32_t bwb = h1b + C2_B_OFF;

    float acc[2][2][4];
#pragma unroll
    for (int f = 0; f < 2; f++)
#pragma unroll
        for (int nt = 0; nt < 2; nt++)
#pragma unroll
            for (int i = 0; i < 4; i++) acc[f][nt][i] = 0.f;

    int y0 = 2 * w;
    int xl = lane & 15, sel = lane >> 4;
    int q = lane >> 3, rowid = lane & 7;

    const int DY[9] = {0, 0, 0, 1, 1, 1, 2, 2, 2};
    const int DX[9] = {0, 1, 2, 0, 1, 2, 0, 1, 2};

    for (int s = 0; s < 18; s++) {
        int tap = s >> 1, ichalf = s & 1;
        int dy = DY[tap], dx = DX[tap];

        uint32_t ah[2][4], al[2][4];
#pragma unroll
        for (int f = 0; f < 2; f++) {
            int pos = (y0 + f + dy) * 18 + (xl + dx);
            uint32_t ad = h1b + (uint32_t)(pos * 80 + ichalf * 32 + sel * 16);
            ldsm_x4(ah[f], ad);
            ldsm_x4(al[f], ad + C2_H1LO);
        }

        uint32_t bh[4], bl[4];
        {
            int koff = s * 16 + (q & 1) * 8;
            uint32_t bd = bwb + (uint32_t)((((q >> 1) * 8 + rowid) * 296 + koff) * 2);
            ldsm_x4(bh, bd);
            ldsm_x4(bl, bd + C2_BPART);
        }

#pragma unroll
        for (int f = 0; f < 2; f++)
#pragma unroll
            for (int nt = 0; nt < 2; nt++) {
                mma16816(acc[f][nt], ah[f], bh[2 * nt], bh[2 * nt + 1]);
                mma16816(acc[f][nt], al[f], bh[2 * nt], bh[2 * nt + 1]);
                mma16816(acc[f][nt], ah[f], bl[2 * nt], bl[2 * nt + 1]);
            }
    }

    // epilogue: y-pool, x-pool, bias, relu, bf16 hi/lo store
    const float* bs2 = (const float*)(sm + C2_BIAS);
    bool active = ((lane >> 2) & 1) == 0;
    int px1 = (lane >> 2) >> 1;
    size_t ob = (size_t)b * 4096 + (size_t)(quarter * 16) * 64 + w * 8;
#pragma unroll
    for (int nt = 0; nt < 2; nt++) {
        int ocl = nt * 8 + (lane & 3) * 2;
        float bA = bs2[ocl], bB = bs2[ocl + 1];
        float v[4];
#pragma unroll
        for (int i = 0; i < 4; i++) {
            float m = fmaxf(acc[0][nt][i], acc[1][nt][i]);
            m = fmaxf(m, __shfl_xor_sync(0xffffffffu, m, 4));
            v[i] = m;
        }
        if (active) {
            float r0 = fmaxf(v[0] + bA, 0.f), r1 = fmaxf(v[1] + bB, 0.f);
            float r2 = fmaxf(v[2] + bA, 0.f), r3 = fmaxf(v[3] + bB, 0.f);
            size_t i00 = ob + (size_t)ocl * 64 + px1;
            size_t i10 = ob + (size_t)(ocl + 1) * 64 + px1;
            __nv_bfloat16 h;
            h = __float2bfloat16(r0); g_h2hi[i00] = h;     g_h2lo[i00] = __float2bfloat16(r0 - __bfloat162float(h));
            h = __float2bfloat16(r1); g_h2hi[i10] = h;     g_h2lo[i10] = __float2bfloat16(r1 - __bfloat162float(h));
            h = __float2bfloat16(r2); g_h2hi[i00 + 4] = h; g_h2lo[i00 + 4] = __float2bfloat16(r2 - __bfloat162float(h));
            h = __float2bfloat16(r3); g_h2hi[i10 + 4] = h; g_h2lo[i10 + 4] = __float2bfloat16(r3 - __bfloat162float(h));
        }
    }
}

// ---------------- Kernel F1: fc1 stage 1 — M=64 tiles x K-quarter ----------
// grid (64, 4, 4): x = sample group, y = expert, z = K-split (1024 K each).
#define FC_A_OFF 36864
#define FC_SMEM  55296

__global__ void __launch_bounds__(256, 2) k_fc1(float* __restrict__ dummy) {
    extern __shared__ __align__(16) char smc[];
    __shared__ int sb[64];

    int g = blockIdx.x, e = blockIdx.y, ks = blockIdx.z, tid = threadIdx.x;
    int lane = tid & 31, w = tid >> 5;
    int cnt = g_count[e];
    if (g * 64 >= cnt) return;
    if (tid < 64) {
        int slot = g * 64 + tid;
        sb[tid] = g_list[e * BATCH + ((slot < cnt) ? slot : (g * 64))];
    }
    __syncthreads();

    uint32_t Wb = smem_u32(smc);
    uint32_t Ab = Wb + FC_A_OFF;
    int q = lane >> 3, rowid = lane & 7;

    float acc[4][2][4];
#pragma unroll
    for (int mf = 0; mf < 4; mf++)
#pragma unroll
        for (int nt = 0; nt < 2; nt++)
#pragma unroll
            for (int i = 0; i < 4; i++) acc[mf][nt][i] = 0.f;

    const uint4* whig = (const uint4*)(g_wf1hi + (size_t)e * 524288);
    const uint4* wlog = (const uint4*)(g_wf1lo + (size_t)e * 524288);

    for (int cc = 0; cc < 16; cc++) {
        int c = ks * 16 + cc;
#pragma unroll
        for (int t = 0; t < 4; t++) {
            int j = t * 256 + tid;
            int n = j >> 3, k8 = j & 7;
            size_t gi = (size_t)n * 512 + c * 8 + k8;
            *(uint4*)(smc + n * 144 + k8 * 16) = whig[gi];
            *(uint4*)(smc + 18432 + n * 144 + k8 * 16) = wlog[gi];
        }
#pragma unroll
        for (int t = 0; t < 2; t++) {
            int j = t * 256 + tid;
            int s = j >> 3, k8 = j & 7;
            size_t gi = (size_t)sb[s] * 4096 + c * 64 + k8 * 8;
            *(uint4*)(smc + FC_A_OFF + s * 144 + k8 * 16) = *(const uint4*)&g_h2hi[gi];
            *(uint4*)(smc + FC_A_OFF + 9216 + s * 144 + k8 * 16) = *(const uint4*)&g_h2lo[gi];
        }
        __syncthreads();

#pragma unroll
        for (int k16 = 0; k16 < 4; k16++) {
            uint32_t bh[4], bl[4];
            uint32_t bd = Wb + (uint32_t)((w * 16 + (q >> 1) * 8 + rowid) * 144 + k16 * 32 + (q & 1) * 16);
            ldsm_x4(bh, bd);
            ldsm_x4(bl, bd + 18432);
#pragma unroll
            for (int mf = 0; mf < 4; mf++) {
                uint32_t ah[4], al[4];
                uint32_t ad = Ab + (uint32_t)((mf * 16 + (lane & 15)) * 144 + k16 * 32 + (lane >> 4) * 16);
                ldsm_x4(ah, ad);
                ldsm_x4(al, ad + 9216);
#pragma unroll
                for (int nt = 0; nt < 2; nt++) {
                    mma16816(acc[mf][nt], ah, bh[2 * nt], bh[2 * nt + 1]);
                    mma16816(acc[mf][nt], al, bh[2 * nt], bh[2 * nt + 1]);
                    mma16816(acc[mf][nt], ah, bl[2 * nt], bl[2 * nt + 1]);
                }
            }
        }
        __syncthreads();
    }

    // write partials (one writer per (b, n): slot-guarded)
    float* pout = g_fc1part + (size_t)ks * (BATCH * 128);
    int r1 = lane >> 2, ccn = 2 * (lane & 3);
#pragma unroll
    for (int mf = 0; mf < 4; mf++) {
        int row0 = mf * 16 + r1, row1 = row0 + 8;
        bool ok0 = (g * 64 + row0) < cnt;
        bool ok1 = (g * 64 + row1) < cnt;
        int b0 = sb[row0], b1 = sb[row1];
#pragma unroll
        for (int nt = 0; nt < 2; nt++) {
            int n = w * 16 + nt * 8 + ccn;
            if (ok0) {
                pout[(size_t)b0 * 128 + n]     = acc[mf][nt][0];
                pout[(size_t)b0 * 128 + n + 1] = acc[mf][nt][1];
            }
            if (ok1) {
                pout[(size_t)b1 * 128 + n]     = acc[mf][nt][2];
                pout[(size_t)b1 * 128 + n + 1] = acc[mf][nt][3];
            }
        }
    }
}

// ---------------- Kernel F2: combine K-splits + bias/relu + fc2 + aux ------
__global__ void __launch_bounds__(256) k_fc2(
    const float* __restrict__ bf1,
    const float* __restrict__ wf2, const float* __restrict__ bf2,
    const float* __restrict__ probs,
    float* __restrict__ out_final, float* __restrict__ out_aux) {
    __shared__ float w2all[5120];
    __shared__ float fs[32 * 129];
    __shared__ float sred[256][4];
    int blk = blockIdx.x, tid = threadIdx.x;

    // aux loss in block 0 (deterministic tree reduce)
    if (blk == 0) {
        float s[4] = {0.f, 0.f, 0.f, 0.f};
        for (int b = tid; b < BATCH; b += 256) {
            float4 p = *(const float4*)&probs[b * 4];
            s[0] += p.x; s[1] += p.y; s[2] += p.z; s[3] += p.w;
        }
#pragma unroll
        for (int k = 0; k < 4; k++) sred[tid][k] = s[k];
        __syncthreads();
        for (int o = 128; o > 0; o >>= 1) {
            if (tid < o)
#pragma unroll
                for (int k = 0; k < 4; k++) sred[tid][k] += sred[tid + o][k];
            __syncthreads();
        }
        if (tid == 0) {
            float a = 0.f;
#pragma unroll
            for (int k = 0; k < 4; k++) {
                float d = sred[0][k] * (1.0f / BATCH) - 0.25f;
                a += d * d;
            }
            out_aux[0] = a * 0.25f;
        }
    }

    for (int i = tid; i < 5120; i += 256) w2all[i] = wf2[i];

    // combine 4 K-partials (fixed order), +bias, relu -> fs
    {
        int si = tid >> 3, seg = tid & 7;
        int b = blk * 32 + si;
        int e = g_expert[b];
        size_t base = (size_t)b * 128 + seg * 16;
#pragma unroll
        for (int qd = 0; qd < 4; qd++) {
            int n = seg * 16 + qd * 4;
            float4 a0 = *(const float4*)&g_fc1part[base + qd * 4];
            float4 a1 = *(const float4*)&g_fc1part[(size_t)BATCH * 128 + base + qd * 4];
            float4 a2 = *(const float4*)&g_fc1part[(size_t)2 * BATCH * 128 + base + qd * 4];
            float4 a3 = *(const float4*)&g_fc1part[(size_t)3 * BATCH * 128 + base + qd * 4];
            float4 bb = *(const float4*)&bf1[e * 128 + n];
            fs[si * 129 + n]     = fmaxf(((a0.x + a1.x) + a2.x) + a3.x + bb.x, 0.f);
            fs[si * 129 + n + 1] = fmaxf(((a0.y + a1.y) + a2.y) + a3.y + bb.y, 0.f);
            fs[si * 129 + n + 2] = fmaxf(((a0.z + a1.z) + a2.z) + a3.z + bb.z, 0.f);
            fs[si * 129 + n + 3] = fmaxf(((a0.w + a1.w) + a2.w) + a3.w + bb.w, 0.f);
        }
    }
    __syncthreads();

    // fc2 + gate scale + scatter
    for (int o = tid; o < 320; o += 256) {
        int si = o / 10, n = o - si * 10;
        int b = blk * 32 + si;
        int e = g_expert[b];
        float a = bf2[e * 10 + n];
        const float* fr = &fs[si * 129];
        const float* wr = &w2all[e * 1280 + n * 128];
#pragma unroll 8
        for (int k = 0; k < 128; k++) a += fr[k] * wr[k];
        out_final[b * 10 + n] = a * g_gatew[b];
    }
}

// ---------------- launch ---------------------------------------------------
extern "C" void kernel_launch(void* const* d_in, const int* in_sizes, int n_in,
                              void* d_out, int out_size) {
    const float* x    = (const float*)d_in[0];
    const float* gwc  = (const float*)d_in[1];
    const float* gbc  = (const float*)d_in[2];
    const float* gwfc = (const float*)d_in[3];
    const float* gbfc = (const float*)d_in[4];
    const float* ew1  = (const float*)d_in[5];
    const float* eb1  = (const float*)d_in[6];
    const float* ew2  = (const float*)d_in[7];
    const float* eb2  = (const float*)d_in[8];
    const float* ewf1 = (const float*)d_in[9];
    const float* ebf1 = (const float*)d_in[10];
    const float* ewf2 = (const float*)d_in[11];
    const float* ebf2 = (const float*)d_in[12];

    float* out       = (float*)d_out;
    float* out_final = out;
    float* out_probs = out + BATCH * 10;
    float* out_aux   = out + BATCH * 10 + BATCH * 4;

    cudaFuncSetAttribute(k_conv2m, cudaFuncAttributeMaxDynamicSharedMemorySize, C2_SMEM);
    cudaFuncSetAttribute(k_fc1,    cudaFuncAttributeMaxDynamicSharedMemorySize, FC_SMEM);

    k_prep<<<2356, 256>>>(ew2, ew1, ewf1);
    k_front<<<BATCH, 256>>>(x, gwc, gbc, gwfc, gbfc, eb1, out_probs);
    k_conv2m<<<dim3(4, BATCH), 256, C2_SMEM>>>(eb2);
    k_fc1<<<dim3(64, 4, 4), 256, FC_SMEM>>>(out_final);
    k_fc2<<<BATCH / 32, 256>>>(ebf1, ewf2, ebf2, out_probs, out_final, out_aux);
}